// round 11
// baseline (speedup 1.0000x reference)
#include <cuda_runtime.h>

#define NN 100000
#define EE 1600000

// ---------------- device scratch (allocation-free) ----------------
__device__ int   g_deg[NN];
__device__ float g_norm[NN];
__device__ __align__(16) float4 g_M[128];   // folded weights: 128 x (3 used + pad)
__device__ __align__(16) float4 g_t[NN];    // norm * (h @ M)
__device__ __align__(16) float4 g_x[NN];    // agg-1 accumulator; .w carries norm^2
__device__ __align__(16) float4 g_s[NN];    // agg-2 accumulator
__device__ __align__(16) float4 g_p[NN];    // precomputed per-node factors

// ---------------- helpers ----------------
__device__ __forceinline__ void red_add_v4(float4* addr, float x, float y, float z) {
    asm volatile("red.global.add.v4.f32 [%0], {%1, %2, %3, %4};"
                 :: "l"(addr), "f"(x), "f"(y), "f"(z), "f"(0.f) : "memory");
}

__device__ __forceinline__ float sigm_tanh(float v) {
    float t;
    asm("tanh.approx.f32 %0, %1;" : "=f"(t) : "f"(0.5f * v));
    return fmaf(0.5f, t, 0.5f);
}

// ---------------- degree histogram (8 edges/thread) ----------------
__global__ void k_hist(const int4* __restrict__ src4) {
    int i = (blockIdx.x * blockDim.x + threadIdx.x) * 2;
    if (i < EE / 4) {
        int4 v = src4[i];
        atomicAdd(&g_deg[v.x], 1);
        atomicAdd(&g_deg[v.y], 1);
        atomicAdd(&g_deg[v.z], 1);
        atomicAdd(&g_deg[v.w], 1);
        int4 w = src4[i + 1];
        atomicAdd(&g_deg[w.x], 1);
        atomicAdd(&g_deg[w.y], 1);
        atomicAdd(&g_deg[w.z], 1);
        atomicAdd(&g_deg[w.w], 1);
    }
}

// ---------------- prep: norm + accumulator init (2 nodes/thread) ----------------
__global__ void __launch_bounds__(512) k_prep() {
    int i = (blockIdx.x * blockDim.x + threadIdx.x) * 2;
    if (i >= NN) return;
    int2 dg = *(const int2*)&g_deg[i];
    float n0 = rsqrtf((float)dg.x);
    float n1 = rsqrtf((float)dg.y);
    *(float2*)&g_norm[i] = make_float2(n0, n1);
    g_x[i]     = make_float4(0.f, 0.f, 0.f, n0 * n0);  // .w = inter-layer scale
    g_x[i + 1] = make_float4(0.f, 0.f, 0.f, n1 * n1);
    g_s[i]     = make_float4(0.f, 0.f, 0.f, 0.f);
    g_s[i + 1] = make_float4(0.f, 0.f, 0.f, 0.f);
}

// ---------------- fold weights: M = W0 @ W1 @ [rowsum(wr0), wr1, wal] -------------
__global__ void k_weights(const float* __restrict__ w0g, const float* __restrict__ w1g,
                          const float* __restrict__ wr0, const float* __restrict__ wr1,
                          const float* __restrict__ wal) {
    __shared__ float V[128][4];
    __shared__ float U[128][4];
    int k = threadIdx.x;  // 128 threads
    const float4* r0v = (const float4*)(wr0 + k * 128);
    float s = 0.f;
#pragma unroll 8
    for (int f = 0; f < 32; f++) {
        float4 v = r0v[f];
        s += v.x + v.y + v.z + v.w;
    }
    V[k][0] = s;
    V[k][1] = wr1[k];
    V[k][2] = wal[k];
    __syncthreads();
    float s0 = 0.f, s1 = 0.f, s2 = 0.f;
    for (int f = 0; f < 128; f++) {
        float w = w1g[k * 128 + f];
        s0 += w * V[f][0]; s1 += w * V[f][1]; s2 += w * V[f][2];
    }
    U[k][0] = s0; U[k][1] = s1; U[k][2] = s2;
    __syncthreads();
    s0 = s1 = s2 = 0.f;
    for (int f = 0; f < 128; f++) {
        float w = w0g[k * 128 + f];
        s0 += w * U[f][0]; s1 += w * U[f][1]; s2 += w * U[f][2];
    }
    g_M[k] = make_float4(s0, s1, s2, 0.f);
}

// ---------------- t = norm * (h @ M)  (HALF-warp per node, 4 nodes/warp) ----------
// grid 3125 x 256: 25000 warps x 4 nodes = 100000 exactly.
// Lane hl (0..15) covers float4 feature-chunks {hl, hl+16}; butterfly over 4 stages.
__global__ void __launch_bounds__(256) k_t(const float4* __restrict__ h4) {
    int lane = threadIdx.x & 31;
    int hl = lane & 15;
    int half = lane >> 4;
    int warp = (blockIdx.x * blockDim.x + threadIdx.x) >> 5;
    int n0 = warp * 4 + half * 2;  // this half-warp's first node
    int n1 = n0 + 1;               // second node

    // M rows for chunk hl (features 4hl..4hl+3) and chunk hl+16 (features 64+4hl..)
    float4 mL0 = g_M[hl * 4 + 0], mL1 = g_M[hl * 4 + 1];
    float4 mL2 = g_M[hl * 4 + 2], mL3 = g_M[hl * 4 + 3];
    float4 mH0 = g_M[64 + hl * 4 + 0], mH1 = g_M[64 + hl * 4 + 1];
    float4 mH2 = g_M[64 + hl * 4 + 2], mH3 = g_M[64 + hl * 4 + 3];

    float4 a0 = __ldg(&h4[(size_t)n0 * 32 + hl]);
    float4 b0 = __ldg(&h4[(size_t)n0 * 32 + hl + 16]);
    float4 a1 = __ldg(&h4[(size_t)n1 * 32 + hl]);
    float4 b1 = __ldg(&h4[(size_t)n1 * 32 + hl + 16]);

    float s[2][3];
    s[0][0] = a0.x * mL0.x + a0.y * mL1.x + a0.z * mL2.x + a0.w * mL3.x
            + b0.x * mH0.x + b0.y * mH1.x + b0.z * mH2.x + b0.w * mH3.x;
    s[0][1] = a0.x * mL0.y + a0.y * mL1.y + a0.z * mL2.y + a0.w * mL3.y
            + b0.x * mH0.y + b0.y * mH1.y + b0.z * mH2.y + b0.w * mH3.y;
    s[0][2] = a0.x * mL0.z + a0.y * mL1.z + a0.z * mL2.z + a0.w * mL3.z
            + b0.x * mH0.z + b0.y * mH1.z + b0.z * mH2.z + b0.w * mH3.z;
    s[1][0] = a1.x * mL0.x + a1.y * mL1.x + a1.z * mL2.x + a1.w * mL3.x
            + b1.x * mH0.x + b1.y * mH1.x + b1.z * mH2.x + b1.w * mH3.x;
    s[1][1] = a1.x * mL0.y + a1.y * mL1.y + a1.z * mL2.y + a1.w * mL3.y
            + b1.x * mH0.y + b1.y * mH1.y + b1.z * mH2.y + b1.w * mH3.y;
    s[1][2] = a1.x * mL0.z + a1.y * mL1.z + a1.z * mL2.z + a1.w * mL3.z
            + b1.x * mH0.z + b1.y * mH1.z + b1.z * mH2.z + b1.w * mH3.z;

    // 4-stage butterfly within each 16-lane half (xor <= 8 never crosses halves);
    // 6 interleaved chains pipeline through the SHFL unit.
#pragma unroll
    for (int o = 8; o; o >>= 1) {
#pragma unroll
        for (int i = 0; i < 2; i++) {
            s[i][0] += __shfl_xor_sync(0xffffffffu, s[i][0], o);
            s[i][1] += __shfl_xor_sync(0xffffffffu, s[i][1], o);
            s[i][2] += __shfl_xor_sync(0xffffffffu, s[i][2], o);
        }
    }

    if (hl == 0) {
        float nm0 = g_norm[n0];
        g_t[n0] = make_float4(s[0][0] * nm0, s[0][1] * nm0, s[0][2] * nm0, 0.f);
        float nm1 = g_norm[n1];
        g_t[n1] = make_float4(s[1][0] * nm1, s[1][1] * nm1, s[1][2] * nm1, 0.f);
    }
}

// ---------------- pass 1: x[src] += t[dst]  (scatter RED, 4 edges/thread) ---------
__global__ void k_agg1(const int4* __restrict__ src4, const int4* __restrict__ dst4) {
    int i = blockIdx.x * blockDim.x + threadIdx.x;
    if (i >= EE / 4) return;
    int4 s = src4[i];
    int4 d = dst4[i];
    float4 va = __ldg(&g_t[d.x]);
    float4 vb = __ldg(&g_t[d.y]);
    float4 vc = __ldg(&g_t[d.z]);
    float4 vd = __ldg(&g_t[d.w]);
    red_add_v4(&g_x[s.x], va.x, va.y, va.z);
    red_add_v4(&g_x[s.y], vb.x, vb.y, vb.z);
    red_add_v4(&g_x[s.z], vc.x, vc.y, vc.z);
    red_add_v4(&g_x[s.w], vd.x, vd.y, vd.z);
}

// ---------------- pass 2: s[src] += x[dst].xyz * x[dst].w  (fused scale) ----------
__global__ void k_agg2(const int4* __restrict__ src4, const int4* __restrict__ dst4) {
    int i = blockIdx.x * blockDim.x + threadIdx.x;
    if (i >= EE / 4) return;
    int4 s = src4[i];
    int4 d = dst4[i];
    float4 va = __ldg(&g_x[d.x]);
    float4 vb = __ldg(&g_x[d.y]);
    float4 vc = __ldg(&g_x[d.z]);
    float4 vd = __ldg(&g_x[d.w]);
    red_add_v4(&g_s[s.x], va.x * va.w, va.y * va.w, va.z * va.w);
    red_add_v4(&g_s[s.y], vb.x * vb.w, vb.y * vb.w, vb.z * vb.w);
    red_add_v4(&g_s[s.z], vc.x * vc.w, vc.y * vc.w, vc.z * vc.w);
    red_add_v4(&g_s[s.w], vd.x * vd.w, vd.y * vd.w, vd.z * vd.w);
}

// ---------------- per-node finish: final norm + exp precompute --------------------
__global__ void k_finish() {
    int i = blockIdx.x * blockDim.x + threadIdx.x;
    if (i >= NN) return;
    float4 a = g_s[i];
    float nm = g_norm[i];
    float fx = a.x * nm, fy = a.y * nm, fz = a.z * nm;
    float4 p;
    p.x = expf(fx);          // e^{r0sum}
    p.y = expf(fy);          // e^{r1}
    p.z = fz;                // alpha scalar (raw)
    p.w = expf(128.f * fy);  // e^{128*r1}
    g_p[i] = p;
}

// ---------------- per-edge outputs [6, E]  (2 edges/thread) -----------------------
__global__ void __launch_bounds__(256) k_edge(const int2* __restrict__ src,
                                              const int2* __restrict__ dst,
                                              const int2* __restrict__ sfk,
                                              const int2* __restrict__ dfk,
                                              float* __restrict__ out) {
    int i = blockIdx.x * blockDim.x + threadIdx.x;
    if (i >= EE / 2) return;
    int2 s2v = src[i];
    int2 d2v = dst[i];
    int2 a2v = sfk[i];
    int2 b2v = dfk[i];
    int a0 = min(a2v.x, NN - 1), a1 = min(a2v.y, NN - 1);  // JAX clamp
    int b0 = min(b2v.x, NN - 1), b1 = min(b2v.y, NN - 1);

    float4 S0 = __ldg(&g_p[s2v.x]);
    float4 S1 = __ldg(&g_p[s2v.y]);
    float4 D0 = __ldg(&g_p[d2v.x]);
    float4 D1 = __ldg(&g_p[d2v.y]);
    float4 A0 = __ldg(&g_p[a0]);
    float4 A1 = __ldg(&g_p[a1]);
    float4 B0 = __ldg(&g_p[b0]);
    float4 B1 = __ldg(&g_p[b1]);

    int e = i * 2;
    float2* o0 = (float2*)(out + e);
    float2* o1 = (float2*)(out + EE + e);
    float2* o2 = (float2*)(out + 2 * EE + e);
    float2* o3 = (float2*)(out + 3 * EE + e);
    float2* o4 = (float2*)(out + 4 * EE + e);
    float2* o5 = (float2*)(out + 5 * EE + e);

    *o0 = make_float2(S0.x * D0.x, S1.x * D1.x);
    *o1 = make_float2(S0.y * D0.y, S1.y * D1.y);
    *o2 = make_float2(sigm_tanh(S0.z * D0.z), sigm_tanh(S1.z * D1.z));
    *o3 = make_float2(A0.x * B0.w, A1.x * B1.w);
    *o4 = make_float2(A0.y * B0.y, A1.y * B1.y);
    *o5 = make_float2(sigm_tanh(S0.z * B0.z), sigm_tanh(S1.z * B1.z));
}

// ---------------- launch ----------------
extern "C" void kernel_launch(void* const* d_in, const int* in_sizes, int n_in,
                              void* d_out, int out_size) {
    const float* h   = (const float*)d_in[0];
    const float* w0g = (const float*)d_in[1];
    const float* w1g = (const float*)d_in[2];
    const float* wr0 = (const float*)d_in[3];
    const float* wr1 = (const float*)d_in[4];
    const float* wal = (const float*)d_in[5];
    const int* esrc  = (const int*)d_in[6];
    const int* edst  = (const int*)d_in[7];
    const int* sfk   = (const int*)d_in[8];
    const int* dfk   = (const int*)d_in[9];
    float* out = (float*)d_out;

    // one-time host-side resources (created on the uncaptured correctness call)
    static cudaStream_t s2 = nullptr;
    static cudaEvent_t ev0 = nullptr, ev2 = nullptr;
    if (!s2) {
        cudaStreamCreateWithFlags(&s2, cudaStreamNonBlocking);
        cudaEventCreateWithFlags(&ev0, cudaEventDisableTiming);
        cudaEventCreateWithFlags(&ev2, cudaEventDisableTiming);
    }

    void* degp = nullptr;
    cudaGetSymbolAddress(&degp, g_deg);

    // fork: s2 folds weights (FMA-bound, 1 block) concurrently with histogram
    cudaEventRecord(ev0, 0);
    cudaStreamWaitEvent(s2, ev0, 0);
    k_weights<<<1, 128, 0, s2>>>(w0g, w1g, wr0, wr1, wal);
    cudaEventRecord(ev2, s2);

    // main: degree histogram -> prep (norm + accumulator init)
    cudaMemsetAsync(degp, 0, NN * sizeof(int), 0);
    k_hist<<<(EE / 8 + 255) / 256, 256>>>((const int4*)esrc);
    k_prep<<<(NN / 2 + 511) / 512, 512>>>();

    // join (weights) then projection t = norm * (h @ M)
    cudaStreamWaitEvent(0, ev2, 0);
    k_t<<<3125, 256>>>((const float4*)h);

    // two scatter-RED aggregation passes (scale fused via g_x.w)
    k_agg1<<<(EE / 4 + 255) / 256, 256>>>((const int4*)esrc, (const int4*)edst);
    k_agg2<<<(EE / 4 + 255) / 256, 256>>>((const int4*)esrc, (const int4*)edst);

    // per-node exp precompute
    k_finish<<<(NN + 255) / 256, 256>>>();

    // per-edge outputs
    k_edge<<<(EE / 2 + 255) / 256, 256>>>((const int2*)esrc, (const int2*)edst,
                                          (const int2*)sfk, (const int2*)dfk, out);
}

// round 12
// speedup vs baseline: 1.0322x; 1.0322x over previous
#include <cuda_runtime.h>

#define NN 100000
#define EE 1600000

// ---------------- device scratch (allocation-free) ----------------
__device__ int   g_deg[NN];
__device__ float g_norm[NN];
__device__ __align__(16) float4 g_M[128];   // folded weights: 128 x (3 used + pad)
__device__ __align__(16) float4 g_t[NN];    // norm * (h @ M)
__device__ __align__(16) float4 g_x[NN];    // agg-1 accumulator; .w carries norm^2
__device__ __align__(16) float4 g_s[NN];    // agg-2 accumulator
__device__ __align__(16) float4 g_p[NN];    // precomputed per-node factors

// ---------------- helpers ----------------
__device__ __forceinline__ void red_add_v4(float4* addr, float x, float y, float z) {
    asm volatile("red.global.add.v4.f32 [%0], {%1, %2, %3, %4};"
                 :: "l"(addr), "f"(x), "f"(y), "f"(z), "f"(0.f) : "memory");
}

__device__ __forceinline__ float sigm_tanh(float v) {
    float t;
    asm("tanh.approx.f32 %0, %1;" : "=f"(t) : "f"(0.5f * v));
    return fmaf(0.5f, t, 0.5f);
}

// ---------------- degree histogram (8 edges/thread) ----------------
__global__ void k_hist(const int4* __restrict__ src4) {
    int i = (blockIdx.x * blockDim.x + threadIdx.x) * 2;
    if (i < EE / 4) {
        int4 v = src4[i];
        atomicAdd(&g_deg[v.x], 1);
        atomicAdd(&g_deg[v.y], 1);
        atomicAdd(&g_deg[v.z], 1);
        atomicAdd(&g_deg[v.w], 1);
        int4 w = src4[i + 1];
        atomicAdd(&g_deg[w.x], 1);
        atomicAdd(&g_deg[w.y], 1);
        atomicAdd(&g_deg[w.z], 1);
        atomicAdd(&g_deg[w.w], 1);
    }
}

// ---------------- prep: norm + accumulator init (2 nodes/thread) ----------------
__global__ void __launch_bounds__(512) k_prep() {
    int i = (blockIdx.x * blockDim.x + threadIdx.x) * 2;
    if (i >= NN) return;
    int2 dg = *(const int2*)&g_deg[i];
    float n0 = rsqrtf((float)dg.x);
    float n1 = rsqrtf((float)dg.y);
    *(float2*)&g_norm[i] = make_float2(n0, n1);
    g_x[i]     = make_float4(0.f, 0.f, 0.f, n0 * n0);  // .w = inter-layer scale
    g_x[i + 1] = make_float4(0.f, 0.f, 0.f, n1 * n1);
    g_s[i]     = make_float4(0.f, 0.f, 0.f, 0.f);
    g_s[i + 1] = make_float4(0.f, 0.f, 0.f, 0.f);
}

// ---------------- fold weights: M = W0 @ W1 @ [rowsum(wr0), wr1, wal] -------------
__global__ void k_weights(const float* __restrict__ w0g, const float* __restrict__ w1g,
                          const float* __restrict__ wr0, const float* __restrict__ wr1,
                          const float* __restrict__ wal) {
    __shared__ float V[128][4];
    __shared__ float U[128][4];
    int k = threadIdx.x;  // 128 threads
    const float4* r0v = (const float4*)(wr0 + k * 128);
    float s = 0.f;
#pragma unroll 8
    for (int f = 0; f < 32; f++) {
        float4 v = r0v[f];
        s += v.x + v.y + v.z + v.w;
    }
    V[k][0] = s;
    V[k][1] = wr1[k];
    V[k][2] = wal[k];
    __syncthreads();
    float s0 = 0.f, s1 = 0.f, s2 = 0.f;
    for (int f = 0; f < 128; f++) {
        float w = w1g[k * 128 + f];
        s0 += w * V[f][0]; s1 += w * V[f][1]; s2 += w * V[f][2];
    }
    U[k][0] = s0; U[k][1] = s1; U[k][2] = s2;
    __syncthreads();
    s0 = s1 = s2 = 0.f;
    for (int f = 0; f < 128; f++) {
        float w = w0g[k * 128 + f];
        s0 += w * U[f][0]; s1 += w * U[f][1]; s2 += w * U[f][2];
    }
    g_M[k] = make_float4(s0, s1, s2, 0.f);
}

// ---------------- t = norm * (h @ M)  (warp per 4 nodes, grid-stride, M in regs) --
// Small grid (592 blocks): M register-load cost amortized over ~21 nodes/warp.
__global__ void __launch_bounds__(256) k_t(const float4* __restrict__ h4) {
    int lane = threadIdx.x & 31;
    int warp = (blockIdx.x * blockDim.x + threadIdx.x) >> 5;
    int nwarps = (gridDim.x * blockDim.x) >> 5;

    float4 m0 = g_M[lane * 4 + 0];
    float4 m1 = g_M[lane * 4 + 1];
    float4 m2 = g_M[lane * 4 + 2];
    float4 m3 = g_M[lane * 4 + 3];

    for (int base = warp * 4; base < NN; base += nwarps * 4) {
        float a[4][3];
#pragma unroll
        for (int j = 0; j < 4; j++) {
            int node = base + j;
            float4 hv = make_float4(0.f, 0.f, 0.f, 0.f);
            if (node < NN) hv = __ldg(&h4[(size_t)node * 32 + lane]);
            a[j][0] = hv.x * m0.x + hv.y * m1.x + hv.z * m2.x + hv.w * m3.x;
            a[j][1] = hv.x * m0.y + hv.y * m1.y + hv.z * m2.y + hv.w * m3.y;
            a[j][2] = hv.x * m0.z + hv.y * m1.z + hv.z * m2.z + hv.w * m3.z;
        }
        // 12 interleaved butterfly chains (independent -> pipelined)
#pragma unroll
        for (int o = 16; o; o >>= 1) {
#pragma unroll
            for (int j = 0; j < 4; j++) {
                a[j][0] += __shfl_xor_sync(0xffffffffu, a[j][0], o);
                a[j][1] += __shfl_xor_sync(0xffffffffu, a[j][1], o);
                a[j][2] += __shfl_xor_sync(0xffffffffu, a[j][2], o);
            }
        }
        if (lane == 0) {
#pragma unroll
            for (int j = 0; j < 4; j++) {
                int node = base + j;
                if (node < NN) {
                    float nm = g_norm[node];
                    g_t[node] = make_float4(a[j][0] * nm, a[j][1] * nm, a[j][2] * nm, 0.f);
                }
            }
        }
    }
}

// ---------------- pass 1: x[src] += t[dst]  (scatter RED, 4 edges/thread) ---------
__global__ void k_agg1(const int4* __restrict__ src4, const int4* __restrict__ dst4) {
    int i = blockIdx.x * blockDim.x + threadIdx.x;
    if (i >= EE / 4) return;
    int4 s = src4[i];
    int4 d = dst4[i];
    float4 va = __ldg(&g_t[d.x]);
    float4 vb = __ldg(&g_t[d.y]);
    float4 vc = __ldg(&g_t[d.z]);
    float4 vd = __ldg(&g_t[d.w]);
    red_add_v4(&g_x[s.x], va.x, va.y, va.z);
    red_add_v4(&g_x[s.y], vb.x, vb.y, vb.z);
    red_add_v4(&g_x[s.z], vc.x, vc.y, vc.z);
    red_add_v4(&g_x[s.w], vd.x, vd.y, vd.z);
}

// ---------------- pass 2: s[src] += x[dst].xyz * x[dst].w  (fused scale) ----------
__global__ void k_agg2(const int4* __restrict__ src4, const int4* __restrict__ dst4) {
    int i = blockIdx.x * blockDim.x + threadIdx.x;
    if (i >= EE / 4) return;
    int4 s = src4[i];
    int4 d = dst4[i];
    float4 va = __ldg(&g_x[d.x]);
    float4 vb = __ldg(&g_x[d.y]);
    float4 vc = __ldg(&g_x[d.z]);
    float4 vd = __ldg(&g_x[d.w]);
    red_add_v4(&g_s[s.x], va.x * va.w, va.y * va.w, va.z * va.w);
    red_add_v4(&g_s[s.y], vb.x * vb.w, vb.y * vb.w, vb.z * vb.w);
    red_add_v4(&g_s[s.z], vc.x * vc.w, vc.y * vc.w, vc.z * vc.w);
    red_add_v4(&g_s[s.w], vd.x * vd.w, vd.y * vd.w, vd.z * vd.w);
}

// ---------------- per-node finish: final norm + exp precompute --------------------
__global__ void k_finish() {
    int i = blockIdx.x * blockDim.x + threadIdx.x;
    if (i >= NN) return;
    float4 a = g_s[i];
    float nm = g_norm[i];
    float fx = a.x * nm, fy = a.y * nm, fz = a.z * nm;
    float4 p;
    p.x = expf(fx);          // e^{r0sum}
    p.y = expf(fy);          // e^{r1}
    p.z = fz;                // alpha scalar (raw)
    p.w = expf(128.f * fy);  // e^{128*r1}
    g_p[i] = p;
}

// ---------------- per-edge outputs [6, E]  (2 edges/thread) -----------------------
__global__ void __launch_bounds__(256) k_edge(const int2* __restrict__ src,
                                              const int2* __restrict__ dst,
                                              const int2* __restrict__ sfk,
                                              const int2* __restrict__ dfk,
                                              float* __restrict__ out) {
    int i = blockIdx.x * blockDim.x + threadIdx.x;
    if (i >= EE / 2) return;
    int2 s2v = src[i];
    int2 d2v = dst[i];
    int2 a2v = sfk[i];
    int2 b2v = dfk[i];
    int a0 = min(a2v.x, NN - 1), a1 = min(a2v.y, NN - 1);  // JAX clamp
    int b0 = min(b2v.x, NN - 1), b1 = min(b2v.y, NN - 1);

    float4 S0 = __ldg(&g_p[s2v.x]);
    float4 S1 = __ldg(&g_p[s2v.y]);
    float4 D0 = __ldg(&g_p[d2v.x]);
    float4 D1 = __ldg(&g_p[d2v.y]);
    float4 A0 = __ldg(&g_p[a0]);
    float4 A1 = __ldg(&g_p[a1]);
    float4 B0 = __ldg(&g_p[b0]);
    float4 B1 = __ldg(&g_p[b1]);

    int e = i * 2;
    float2* o0 = (float2*)(out + e);
    float2* o1 = (float2*)(out + EE + e);
    float2* o2 = (float2*)(out + 2 * EE + e);
    float2* o3 = (float2*)(out + 3 * EE + e);
    float2* o4 = (float2*)(out + 4 * EE + e);
    float2* o5 = (float2*)(out + 5 * EE + e);

    *o0 = make_float2(S0.x * D0.x, S1.x * D1.x);
    *o1 = make_float2(S0.y * D0.y, S1.y * D1.y);
    *o2 = make_float2(sigm_tanh(S0.z * D0.z), sigm_tanh(S1.z * D1.z));
    *o3 = make_float2(A0.x * B0.w, A1.x * B1.w);
    *o4 = make_float2(A0.y * B0.y, A1.y * B1.y);
    *o5 = make_float2(sigm_tanh(S0.z * B0.z), sigm_tanh(S1.z * B1.z));
}

// ---------------- launch ----------------
extern "C" void kernel_launch(void* const* d_in, const int* in_sizes, int n_in,
                              void* d_out, int out_size) {
    const float* h   = (const float*)d_in[0];
    const float* w0g = (const float*)d_in[1];
    const float* w1g = (const float*)d_in[2];
    const float* wr0 = (const float*)d_in[3];
    const float* wr1 = (const float*)d_in[4];
    const float* wal = (const float*)d_in[5];
    const int* esrc  = (const int*)d_in[6];
    const int* edst  = (const int*)d_in[7];
    const int* sfk   = (const int*)d_in[8];
    const int* dfk   = (const int*)d_in[9];
    float* out = (float*)d_out;

    // one-time host-side resources (created on the uncaptured correctness call)
    static cudaStream_t s2 = nullptr;
    static cudaEvent_t ev0 = nullptr, ev2 = nullptr;
    if (!s2) {
        cudaStreamCreateWithFlags(&s2, cudaStreamNonBlocking);
        cudaEventCreateWithFlags(&ev0, cudaEventDisableTiming);
        cudaEventCreateWithFlags(&ev2, cudaEventDisableTiming);
    }

    void* degp = nullptr;
    cudaGetSymbolAddress(&degp, g_deg);

    // fork: s2 folds weights (FMA-bound, 1 block) concurrently with histogram
    cudaEventRecord(ev0, 0);
    cudaStreamWaitEvent(s2, ev0, 0);
    k_weights<<<1, 128, 0, s2>>>(w0g, w1g, wr0, wr1, wal);
    cudaEventRecord(ev2, s2);

    // main: degree histogram -> prep (norm + accumulator init)
    cudaMemsetAsync(degp, 0, NN * sizeof(int), 0);
    k_hist<<<(EE / 8 + 255) / 256, 256>>>((const int4*)esrc);
    k_prep<<<(NN / 2 + 511) / 512, 512>>>();

    // join (weights) then projection t = norm * (h @ M)
    cudaStreamWaitEvent(0, ev2, 0);
    k_t<<<592, 256>>>((const float4*)h);

    // two scatter-RED aggregation passes (scale fused via g_x.w)
    k_agg1<<<(EE / 4 + 255) / 256, 256>>>((const int4*)esrc, (const int4*)edst);
    k_agg2<<<(EE / 4 + 255) / 256, 256>>>((const int4*)esrc, (const int4*)edst);

    // per-node exp precompute
    k_finish<<<(NN + 255) / 256, 256>>>();

    // per-edge outputs
    k_edge<<<(EE / 2 + 255) / 256, 256>>>((const int2*)esrc, (const int2*)edst,
                                          (const int2*)sfk, (const int2*)dfk, out);
}

// round 13
// speedup vs baseline: 1.0496x; 1.0169x over previous
#include <cuda_runtime.h>

#define NN 100000
#define EE 1600000

// ---------------- device scratch (allocation-free) ----------------
__device__ int   g_deg[NN];
__device__ float g_norm[NN];
__device__ __align__(16) float4 g_M[128];   // folded weights: 128 x (3 used + pad)
__device__ __align__(16) float4 g_t[NN];    // norm * (h @ M)
__device__ __align__(16) float4 g_x[NN];    // agg-1 accumulator; .w carries norm^2
__device__ __align__(16) float4 g_s[NN];    // agg-2 accumulator
__device__ __align__(16) float4 g_p[NN];    // precomputed per-node factors

// ---------------- helpers ----------------
__device__ __forceinline__ void red_add_v4(float4* addr, float x, float y, float z) {
    asm volatile("red.global.add.v4.f32 [%0], {%1, %2, %3, %4};"
                 :: "l"(addr), "f"(x), "f"(y), "f"(z), "f"(0.f) : "memory");
}

__device__ __forceinline__ float sigm_tanh(float v) {
    float t;
    asm("tanh.approx.f32 %0, %1;" : "=f"(t) : "f"(0.5f * v));
    return fmaf(0.5f, t, 0.5f);
}

// ---------------- degree histogram (8 edges/thread) ----------------
__global__ void k_hist(const int4* __restrict__ src4) {
    int i = (blockIdx.x * blockDim.x + threadIdx.x) * 2;
    if (i < EE / 4) {
        int4 v = src4[i];
        atomicAdd(&g_deg[v.x], 1);
        atomicAdd(&g_deg[v.y], 1);
        atomicAdd(&g_deg[v.z], 1);
        atomicAdd(&g_deg[v.w], 1);
        int4 w = src4[i + 1];
        atomicAdd(&g_deg[w.x], 1);
        atomicAdd(&g_deg[w.y], 1);
        atomicAdd(&g_deg[w.z], 1);
        atomicAdd(&g_deg[w.w], 1);
    }
}

// ---------------- prep: norm + accumulator init (2 nodes/thread) ----------------
__global__ void __launch_bounds__(512) k_prep() {
    int i = (blockIdx.x * blockDim.x + threadIdx.x) * 2;
    if (i >= NN) return;
    int2 dg = *(const int2*)&g_deg[i];
    float n0 = rsqrtf((float)dg.x);
    float n1 = rsqrtf((float)dg.y);
    *(float2*)&g_norm[i] = make_float2(n0, n1);
    g_x[i]     = make_float4(0.f, 0.f, 0.f, n0 * n0);  // .w = inter-layer scale
    g_x[i + 1] = make_float4(0.f, 0.f, 0.f, n1 * n1);
    g_s[i]     = make_float4(0.f, 0.f, 0.f, 0.f);
    g_s[i + 1] = make_float4(0.f, 0.f, 0.f, 0.f);
}

// ---------------- fold weights: M = W0 @ W1 @ [rowsum(wr0), wr1, wal] -------------
__global__ void k_weights(const float* __restrict__ w0g, const float* __restrict__ w1g,
                          const float* __restrict__ wr0, const float* __restrict__ wr1,
                          const float* __restrict__ wal) {
    __shared__ float V[128][4];
    __shared__ float U[128][4];
    int k = threadIdx.x;  // 128 threads
    const float4* r0v = (const float4*)(wr0 + k * 128);
    float s = 0.f;
#pragma unroll 8
    for (int f = 0; f < 32; f++) {
        float4 v = r0v[f];
        s += v.x + v.y + v.z + v.w;
    }
    V[k][0] = s;
    V[k][1] = wr1[k];
    V[k][2] = wal[k];
    __syncthreads();
    float s0 = 0.f, s1 = 0.f, s2 = 0.f;
    for (int f = 0; f < 128; f++) {
        float w = w1g[k * 128 + f];
        s0 += w * V[f][0]; s1 += w * V[f][1]; s2 += w * V[f][2];
    }
    U[k][0] = s0; U[k][1] = s1; U[k][2] = s2;
    __syncthreads();
    s0 = s1 = s2 = 0.f;
    for (int f = 0; f < 128; f++) {
        float w = w0g[k * 128 + f];
        s0 += w * U[f][0]; s1 += w * U[f][1]; s2 += w * U[f][2];
    }
    g_M[k] = make_float4(s0, s1, s2, 0.f);
}

// ---------------- t = norm * (h @ M) ----------------------------------------------
// Grid-stride (M amortized over ~21 iters/warp) + half-warp-per-node butterfly:
// lane hl (0..15) covers feature chunks {hl, hl+16}; 4 stages, 2 nodes per SHFL.
// NN % 4 == 0 -> no bounds checks inside the loop.
__global__ void __launch_bounds__(256) k_t(const float4* __restrict__ h4) {
    int lane = threadIdx.x & 31;
    int hl = lane & 15;
    int half = lane >> 4;
    int warp = (blockIdx.x * blockDim.x + threadIdx.x) >> 5;
    int nwarps = (gridDim.x * blockDim.x) >> 5;

    float4 mL0 = g_M[hl * 4 + 0], mL1 = g_M[hl * 4 + 1];
    float4 mL2 = g_M[hl * 4 + 2], mL3 = g_M[hl * 4 + 3];
    float4 mH0 = g_M[64 + hl * 4 + 0], mH1 = g_M[64 + hl * 4 + 1];
    float4 mH2 = g_M[64 + hl * 4 + 2], mH3 = g_M[64 + hl * 4 + 3];

    for (int base = warp * 4; base < NN; base += nwarps * 4) {
        int n0 = base + half * 2;
        int n1 = n0 + 1;

        float4 a0 = __ldg(&h4[(size_t)n0 * 32 + hl]);
        float4 b0 = __ldg(&h4[(size_t)n0 * 32 + hl + 16]);
        float4 a1 = __ldg(&h4[(size_t)n1 * 32 + hl]);
        float4 b1 = __ldg(&h4[(size_t)n1 * 32 + hl + 16]);

        float s[2][3];
        s[0][0] = a0.x * mL0.x + a0.y * mL1.x + a0.z * mL2.x + a0.w * mL3.x
                + b0.x * mH0.x + b0.y * mH1.x + b0.z * mH2.x + b0.w * mH3.x;
        s[0][1] = a0.x * mL0.y + a0.y * mL1.y + a0.z * mL2.y + a0.w * mL3.y
                + b0.x * mH0.y + b0.y * mH1.y + b0.z * mH2.y + b0.w * mH3.y;
        s[0][2] = a0.x * mL0.z + a0.y * mL1.z + a0.z * mL2.z + a0.w * mL3.z
                + b0.x * mH0.z + b0.y * mH1.z + b0.z * mH2.z + b0.w * mH3.z;
        s[1][0] = a1.x * mL0.x + a1.y * mL1.x + a1.z * mL2.x + a1.w * mL3.x
                + b1.x * mH0.x + b1.y * mH1.x + b1.z * mH2.x + b1.w * mH3.x;
        s[1][1] = a1.x * mL0.y + a1.y * mL1.y + a1.z * mL2.y + a1.w * mL3.y
                + b1.x * mH0.y + b1.y * mH1.y + b1.z * mH2.y + b1.w * mH3.y;
        s[1][2] = a1.x * mL0.z + a1.y * mL1.z + a1.z * mL2.z + a1.w * mL3.z
                + b1.x * mH0.z + b1.y * mH1.z + b1.z * mH2.z + b1.w * mH3.z;

        // 4-stage butterfly within each 16-lane half (xor <= 8 stays in-half)
#pragma unroll
        for (int o = 8; o; o >>= 1) {
#pragma unroll
            for (int i = 0; i < 2; i++) {
                s[i][0] += __shfl_xor_sync(0xffffffffu, s[i][0], o);
                s[i][1] += __shfl_xor_sync(0xffffffffu, s[i][1], o);
                s[i][2] += __shfl_xor_sync(0xffffffffu, s[i][2], o);
            }
        }

        if (hl == 0) {
            float nm0 = g_norm[n0];
            g_t[n0] = make_float4(s[0][0] * nm0, s[0][1] * nm0, s[0][2] * nm0, 0.f);
            float nm1 = g_norm[n1];
            g_t[n1] = make_float4(s[1][0] * nm1, s[1][1] * nm1, s[1][2] * nm1, 0.f);
        }
    }
}

// ---------------- pass 1: x[src] += t[dst]  (scatter RED, 4 edges/thread) ---------
__global__ void k_agg1(const int4* __restrict__ src4, const int4* __restrict__ dst4) {
    int i = blockIdx.x * blockDim.x + threadIdx.x;
    if (i >= EE / 4) return;
    int4 s = src4[i];
    int4 d = dst4[i];
    float4 va = __ldg(&g_t[d.x]);
    float4 vb = __ldg(&g_t[d.y]);
    float4 vc = __ldg(&g_t[d.z]);
    float4 vd = __ldg(&g_t[d.w]);
    red_add_v4(&g_x[s.x], va.x, va.y, va.z);
    red_add_v4(&g_x[s.y], vb.x, vb.y, vb.z);
    red_add_v4(&g_x[s.z], vc.x, vc.y, vc.z);
    red_add_v4(&g_x[s.w], vd.x, vd.y, vd.z);
}

// ---------------- pass 2: s[src] += x[dst].xyz * x[dst].w  (fused scale) ----------
__global__ void k_agg2(const int4* __restrict__ src4, const int4* __restrict__ dst4) {
    int i = blockIdx.x * blockDim.x + threadIdx.x;
    if (i >= EE / 4) return;
    int4 s = src4[i];
    int4 d = dst4[i];
    float4 va = __ldg(&g_x[d.x]);
    float4 vb = __ldg(&g_x[d.y]);
    float4 vc = __ldg(&g_x[d.z]);
    float4 vd = __ldg(&g_x[d.w]);
    red_add_v4(&g_s[s.x], va.x * va.w, va.y * va.w, va.z * va.w);
    red_add_v4(&g_s[s.y], vb.x * vb.w, vb.y * vb.w, vb.z * vb.w);
    red_add_v4(&g_s[s.z], vc.x * vc.w, vc.y * vc.w, vc.z * vc.w);
    red_add_v4(&g_s[s.w], vd.x * vd.w, vd.y * vd.w, vd.z * vd.w);
}

// ---------------- per-node finish: final norm + exp precompute --------------------
__global__ void k_finish() {
    int i = blockIdx.x * blockDim.x + threadIdx.x;
    if (i >= NN) return;
    float4 a = g_s[i];
    float nm = g_norm[i];
    float fx = a.x * nm, fy = a.y * nm, fz = a.z * nm;
    float4 p;
    p.x = expf(fx);          // e^{r0sum}
    p.y = expf(fy);          // e^{r1}
    p.z = fz;                // alpha scalar (raw)
    p.w = expf(128.f * fy);  // e^{128*r1}
    g_p[i] = p;
}

// ---------------- per-edge outputs [6, E]  (4 edges/thread, float4 stores) --------
__global__ void __launch_bounds__(256) k_edge(const int4* __restrict__ src,
                                              const int4* __restrict__ dst,
                                              const int4* __restrict__ sfk,
                                              const int4* __restrict__ dfk,
                                              float* __restrict__ out) {
    int i = blockIdx.x * blockDim.x + threadIdx.x;
    if (i >= EE / 4) return;
    int4 sv = src[i];
    int4 dv = dst[i];
    int4 av = sfk[i];
    int4 bv = dfk[i];
    av.x = min(av.x, NN - 1); av.y = min(av.y, NN - 1);  // JAX gather clamps
    av.z = min(av.z, NN - 1); av.w = min(av.w, NN - 1);
    bv.x = min(bv.x, NN - 1); bv.y = min(bv.y, NN - 1);
    bv.z = min(bv.z, NN - 1); bv.w = min(bv.w, NN - 1);

    float4 S0 = __ldg(&g_p[sv.x]), S1 = __ldg(&g_p[sv.y]);
    float4 S2 = __ldg(&g_p[sv.z]), S3 = __ldg(&g_p[sv.w]);
    float4 D0 = __ldg(&g_p[dv.x]), D1 = __ldg(&g_p[dv.y]);
    float4 D2 = __ldg(&g_p[dv.z]), D3 = __ldg(&g_p[dv.w]);
    float4 A0 = __ldg(&g_p[av.x]), A1 = __ldg(&g_p[av.y]);
    float4 A2 = __ldg(&g_p[av.z]), A3 = __ldg(&g_p[av.w]);
    float4 B0 = __ldg(&g_p[bv.x]), B1 = __ldg(&g_p[bv.y]);
    float4 B2 = __ldg(&g_p[bv.z]), B3 = __ldg(&g_p[bv.w]);

    int e = i * 4;
    *(float4*)(out + e) =
        make_float4(S0.x * D0.x, S1.x * D1.x, S2.x * D2.x, S3.x * D3.x);
    *(float4*)(out + EE + e) =
        make_float4(S0.y * D0.y, S1.y * D1.y, S2.y * D2.y, S3.y * D3.y);
    *(float4*)(out + 2 * EE + e) =
        make_float4(sigm_tanh(S0.z * D0.z), sigm_tanh(S1.z * D1.z),
                    sigm_tanh(S2.z * D2.z), sigm_tanh(S3.z * D3.z));
    *(float4*)(out + 3 * EE + e) =
        make_float4(A0.x * B0.w, A1.x * B1.w, A2.x * B2.w, A3.x * B3.w);
    *(float4*)(out + 4 * EE + e) =
        make_float4(A0.y * B0.y, A1.y * B1.y, A2.y * B2.y, A3.y * B3.y);
    *(float4*)(out + 5 * EE + e) =
        make_float4(sigm_tanh(S0.z * B0.z), sigm_tanh(S1.z * B1.z),
                    sigm_tanh(S2.z * B2.z), sigm_tanh(S3.z * B3.z));
}

// ---------------- launch ----------------
extern "C" void kernel_launch(void* const* d_in, const int* in_sizes, int n_in,
                              void* d_out, int out_size) {
    const float* h   = (const float*)d_in[0];
    const float* w0g = (const float*)d_in[1];
    const float* w1g = (const float*)d_in[2];
    const float* wr0 = (const float*)d_in[3];
    const float* wr1 = (const float*)d_in[4];
    const float* wal = (const float*)d_in[5];
    const int* esrc  = (const int*)d_in[6];
    const int* edst  = (const int*)d_in[7];
    const int* sfk   = (const int*)d_in[8];
    const int* dfk   = (const int*)d_in[9];
    float* out = (float*)d_out;

    // one-time host-side resources (created on the uncaptured correctness call)
    static cudaStream_t s2 = nullptr;
    static cudaEvent_t ev0 = nullptr, ev2 = nullptr;
    if (!s2) {
        cudaStreamCreateWithFlags(&s2, cudaStreamNonBlocking);
        cudaEventCreateWithFlags(&ev0, cudaEventDisableTiming);
        cudaEventCreateWithFlags(&ev2, cudaEventDisableTiming);
    }

    void* degp = nullptr;
    cudaGetSymbolAddress(&degp, g_deg);

    // fork: s2 folds weights (FMA-bound, 1 block) concurrently with histogram
    cudaEventRecord(ev0, 0);
    cudaStreamWaitEvent(s2, ev0, 0);
    k_weights<<<1, 128, 0, s2>>>(w0g, w1g, wr0, wr1, wal);
    cudaEventRecord(ev2, s2);

    // main: degree histogram -> prep (norm + accumulator init)
    cudaMemsetAsync(degp, 0, NN * sizeof(int), 0);
    k_hist<<<(EE / 8 + 255) / 256, 256>>>((const int4*)esrc);
    k_prep<<<(NN / 2 + 511) / 512, 512>>>();

    // join (weights) then projection t = norm * (h @ M)
    cudaStreamWaitEvent(0, ev2, 0);
    k_t<<<592, 256>>>((const float4*)h);

    // two scatter-RED aggregation passes (scale fused via g_x.w)
    k_agg1<<<(EE / 4 + 255) / 256, 256>>>((const int4*)esrc, (const int4*)edst);
    k_agg2<<<(EE / 4 + 255) / 256, 256>>>((const int4*)esrc, (const int4*)edst);

    // per-node exp precompute
    k_finish<<<(NN + 255) / 256, 256>>>();

    // per-edge outputs
    k_edge<<<(EE / 4 + 255) / 256, 256>>>((const int4*)esrc, (const int4*)edst,
                                          (const int4*)sfk, (const int4*)dfk, out);
}